// round 2
// baseline (speedup 1.0000x reference)
#include <cuda_runtime.h>

// ---------------------------------------------------------------------------
// ChnAttn: 1-query multi-head channel attention over 5 modality tokens.
//
// Algebraic restructuring:
//   logits[p,n,h] = t[p,n,:] . wq[:,h] + cq[h]      (wq = W_in^T W_k^T q*s)
//   v[p,n,:]      = W_vin t[p,n,:] + b_vin          (W_vin = W_v W_in)
//   vw[p,:]       = sum_n softmax(logits)[h(a),n] * v[p,n,a]   (+ b_vin, sum attn = 1)
//   out[p,:]      = (W_out vw[p,:] + b_out) * has_encoder[p]
// ---------------------------------------------------------------------------

#define BN_POS   8192
#define D_DIM    768
#define A_DIM    256
#define NHEAD    8
#define SCALE    0.17677669529663687f   // 1/sqrt(32)
#define OUT_MAIN (8192*768)

// ---- device globals (scratch; no allocation allowed) ----------------------
__device__ float              g_u[A_DIM * NHEAD];      // W_k^T q_s  [j][h]
__device__ float              g_cqa[NHEAD];            // q_s . b_k per head
__device__ float              g_cq[NHEAD];             // final logit constant
__device__ float              g_wq[D_DIM * NHEAD];     // [d][h]
__device__ unsigned long long g_Wvp[D_DIM * 128];      // W_vin paired: [d][p][t] = (W[a=t+64p], W[a=t+64p+32])
__device__ float              g_bvin[A_DIM];
__device__ float              g_WoutT[A_DIM * D_DIM];  // [a][d]
__device__ float              g_vw[BN_POS * A_DIM];
__device__ float              g_hasenc[BN_POS];

// ---- packed f32x2 helpers -------------------------------------------------
__device__ __forceinline__ unsigned long long pack2(float lo, float hi) {
    unsigned long long r;
    asm("mov.b64 %0, {%1, %2};" : "=l"(r) : "f"(lo), "f"(hi));
    return r;
}
__device__ __forceinline__ void unpack2(unsigned long long v, float &lo, float &hi) {
    asm("mov.b64 {%0, %1}, %2;" : "=f"(lo), "=f"(hi) : "l"(v));
}
__device__ __forceinline__ void fma2(unsigned long long &d,
                                     unsigned long long a, unsigned long long b) {
    asm("fma.rn.f32x2 %0, %1, %2, %0;" : "+l"(d) : "l"(a), "l"(b));
}

// ---------------------------------------------------------------------------
// K_u: u[j][h] = sum_{i in head h} q[i]*s * W_k[i][j];  cq partial; b_vin
// ---------------------------------------------------------------------------
__global__ void k_u(const float* __restrict__ Wk, const float* __restrict__ bk,
                    const float* __restrict__ Wv, const float* __restrict__ bv,
                    const float* __restrict__ b_in, const float* __restrict__ query) {
    int j = threadIdx.x;   // 0..255
    #pragma unroll
    for (int h = 0; h < NHEAD; h++) {
        float acc = 0.f;
        #pragma unroll 8
        for (int i = 0; i < 32; i++) {
            float qs = query[h * 32 + i] * SCALE;
            acc += qs * Wk[(h * 32 + i) * A_DIM + j];
        }
        g_u[j * NHEAD + h] = acc;
    }
    if (j < NHEAD) {
        float c = 0.f;
        for (int i = 0; i < 32; i++)
            c += query[j * 32 + i] * SCALE * bk[j * 32 + i];
        g_cqa[j] = c;
    }
    float acc = 0.f;
    for (int c = 0; c < A_DIM; c++) acc += Wv[j * A_DIM + c] * b_in[c];
    g_bvin[j] = acc + bv[j];
}

// ---------------------------------------------------------------------------
// K_wq: wq[d][h] = sum_j W_in[j][d] * u[j][h];  block0 also finalizes cq
// ---------------------------------------------------------------------------
__global__ void k_wq(const float* __restrict__ Win, const float* __restrict__ b_in) {
    int d = blockIdx.x * 32 + (threadIdx.x >> 3);
    int h = threadIdx.x & 7;
    float acc = 0.f;
    #pragma unroll 8
    for (int j = 0; j < A_DIM; j++)
        acc += Win[j * D_DIM + d] * g_u[j * NHEAD + h];
    g_wq[d * NHEAD + h] = acc;
    if (blockIdx.x == 0 && threadIdx.x < NHEAD) {
        float c = g_cqa[threadIdx.x];
        for (int j = 0; j < A_DIM; j++)
            c += b_in[j] * g_u[j * NHEAD + threadIdx.x];
        g_cq[threadIdx.x] = c;
    }
}

// ---------------------------------------------------------------------------
// K_wvin: W_vin = W_v @ W_in  -> paired layout g_Wvp.  grid (4,12), 256 thr.
// ---------------------------------------------------------------------------
__global__ void k_wvin(const float* __restrict__ Wv, const float* __restrict__ Win) {
    __shared__ float sWvT[32 * 65];   // [c][a] padded
    __shared__ float sWin[32 * 64];   // [c][d]
    int tid = threadIdx.x, tx = tid & 31, ty = tid >> 5;
    int a0 = blockIdx.x * 64, d0 = blockIdx.y * 64;
    float acc0[8], acc1[8];
    #pragma unroll
    for (int j = 0; j < 8; j++) { acc0[j] = 0.f; acc1[j] = 0.f; }

    for (int c0 = 0; c0 < A_DIM; c0 += 32) {
        #pragma unroll
        for (int i = tid; i < 2048; i += 256) {
            int kk = i & 31, row = i >> 5;
            sWvT[kk * 65 + row] = Wv[(a0 + row) * A_DIM + c0 + kk];
        }
        #pragma unroll
        for (int i = tid; i < 2048; i += 256) {
            int dd = i & 63, kk = i >> 6;
            sWin[kk * 64 + dd] = Win[(c0 + kk) * D_DIM + d0 + dd];
        }
        __syncthreads();
        #pragma unroll
        for (int k = 0; k < 32; k++) {
            float av0 = sWvT[k * 65 + tx];
            float av1 = sWvT[k * 65 + tx + 32];
            #pragma unroll
            for (int j = 0; j < 8; j++) {
                float b = sWin[k * 64 + ty * 8 + j];
                acc0[j] += av0 * b;
                acc1[j] += av1 * b;
            }
        }
        __syncthreads();
    }
    int p = a0 >> 6;
    #pragma unroll
    for (int j = 0; j < 8; j++) {
        int d = d0 + ty * 8 + j;
        g_Wvp[d * 128 + p * 32 + tx] = pack2(acc0[j], acc1[j]);
    }
}

// ---------------------------------------------------------------------------
// K_woutT: transpose W_out (D,A) -> [a][d]
// ---------------------------------------------------------------------------
__global__ void k_woutT(const float* __restrict__ Wout) {
    int base = blockIdx.x * 1024 + threadIdx.x;
    #pragma unroll
    for (int r = 0; r < 4; r++) {
        int idx = base + r * 256;
        int d = idx >> 8, a = idx & 255;
        g_WoutT[a * D_DIM + d] = Wout[idx];
    }
}

// ---------------------------------------------------------------------------
// K_main: per-block 8 positions. V-GEMM (40 x 256, K=768) + logits (8 heads)
// fused with softmax + attention-weighted sum. Packed f32x2 throughout.
// ---------------------------------------------------------------------------
__global__ __launch_bounds__(256, 2) void k_main(
    const float* __restrict__ s2, const float* __restrict__ s1,
    const int* __restrict__ s2m, const int* __restrict__ s1m,
    float* __restrict__ dout, int write_mask)
{
    __shared__ unsigned long long sA2[40 * 32];    // tokens duplicated (a,a)
    __shared__ unsigned long long sBp[32 * 128];   // W_vin pairs [kk][p][t]
    __shared__ unsigned long long sWq2[32 * 8];    // (wq, 0) pairs
    __shared__ float sLogit[8 * 8 * 5];            // logits then attn, in place

    int tid = threadIdx.x;
    int tx = tid & 31, ty = tid >> 5;
    int h = tx & 7;
    int p0 = blockIdx.x * 8;

    unsigned long long vacc[5][4];
    unsigned long long lacc[5];
    #pragma unroll
    for (int n = 0; n < 5; n++) {
        lacc[n] = 0ull;
        #pragma unroll
        for (int p = 0; p < 4; p++) vacc[n][p] = 0ull;
    }

    for (int k0 = 0; k0 < D_DIM; k0 += 32) {
        // tokens -> smem (duplicated lanes for packed broadcast)
        #pragma unroll
        for (int i = tid; i < 1280; i += 256) {
            int row = i >> 5, kk = i & 31;
            int pos = p0 + row / 5;
            int n   = row - (row / 5) * 5;
            float v = (n < 3) ? s2[(pos * 3 + n) * D_DIM + k0 + kk]
                              : s1[(pos * 2 + n - 3) * D_DIM + k0 + kk];
            sA2[i] = pack2(v, v);
        }
        // W_vin pair tile (straight copy, already paired)
        #pragma unroll
        for (int i = tid; i < 4096; i += 256)
            sBp[i] = g_Wvp[(k0 << 7) + i];
        // wq tile, hi lane = 0 so logit FMA2 is harmless in hi lane
        {
            int kk = tid >> 3, hh = tid & 7;
            sWq2[tid] = pack2(g_wq[(k0 + kk) * 8 + hh], 0.f);
        }
        __syncthreads();

        int abase = ty * 5 * 32;
        #pragma unroll
        for (int kk = 0; kk < 32; kk++) {
            unsigned long long b0 = sBp[kk * 128 + tx];
            unsigned long long b1 = sBp[kk * 128 + 32 + tx];
            unsigned long long b2 = sBp[kk * 128 + 64 + tx];
            unsigned long long b3 = sBp[kk * 128 + 96 + tx];
            unsigned long long w  = sWq2[kk * 8 + h];
            #pragma unroll
            for (int n = 0; n < 5; n++) {
                unsigned long long a = sA2[abase + n * 32 + kk];
                fma2(vacc[n][0], a, b0);
                fma2(vacc[n][1], a, b1);
                fma2(vacc[n][2], a, b2);
                fma2(vacc[n][3], a, b3);
                fma2(lacc[n], a, w);
            }
        }
        __syncthreads();
    }

    // logits to smem (tx<8 hold the canonical copy; others are duplicates)
    if (tx < 8) {
        #pragma unroll
        for (int n = 0; n < 5; n++) {
            float lo, hi; unpack2(lacc[n], lo, hi);
            sLogit[(ty * 8 + tx) * 5 + n] = lo;
        }
    }
    __syncthreads();

    // masked softmax, one thread per (position, head)
    if (tid < 64) {
        int ty2 = tid >> 3, h2 = tid & 7;
        int pos = p0 + ty2;
        int m[5];
        m[0] = s2m[pos * 3 + 0];
        m[1] = s2m[pos * 3 + 1];
        m[2] = s2m[pos * 3 + 2];
        m[3] = s1m[pos * 2 + 0];
        m[4] = s1m[pos * 2 + 1];
        bool has = false;
        float lg[5];
        float cq = g_cq[h2];
        #pragma unroll
        for (int n = 0; n < 5; n++) {
            float L = sLogit[(ty2 * 8 + h2) * 5 + n] + cq;
            if (m[n] == 1) has = true; else L = -1e30f;
            lg[n] = L;
        }
        float mx = lg[0];
        #pragma unroll
        for (int n = 1; n < 5; n++) mx = fmaxf(mx, lg[n]);
        float e[5], s = 0.f;
        #pragma unroll
        for (int n = 0; n < 5; n++) { e[n] = expf(lg[n] - mx); s += e[n]; }
        float inv = 1.f / s;
        #pragma unroll
        for (int n = 0; n < 5; n++)
            sLogit[(ty2 * 8 + h2) * 5 + n] = e[n] * inv;
        if (h2 == 0) {
            float hf = has ? 1.f : 0.f;
            g_hasenc[pos] = hf;
            if (write_mask) dout[OUT_MAIN + pos] = hf;
        }
    }
    __syncthreads();

    // attention-weighted sum of V (+ b_vin; sum(attn)=1 so bias folds in)
    int pos = p0 + ty;
    #pragma unroll
    for (int p = 0; p < 4; p++) {
        unsigned long long acc = pack2(g_bvin[tx + 64 * p], g_bvin[tx + 64 * p + 32]);
        #pragma unroll
        for (int n = 0; n < 5; n++) {
            unsigned long long a2 = pack2(sLogit[(ty * 8 + 2 * p) * 5 + n],
                                          sLogit[(ty * 8 + 2 * p + 1) * 5 + n]);
            fma2(acc, a2, vacc[n][p]);
        }
        float lo, hi; unpack2(acc, lo, hi);
        g_vw[pos * A_DIM + tx + 64 * p]      = lo;
        g_vw[pos * A_DIM + tx + 64 * p + 32] = hi;
    }
}

// ---------------------------------------------------------------------------
// K_out: out = vw (8192x256) @ W_out^T (256x768) + b_out, masked.
// BM=32 pos, BN=128 d, BK=32. Packed over position pairs.
// ---------------------------------------------------------------------------
__global__ __launch_bounds__(256, 4) void k_out(const float* __restrict__ b_out,
                                                float* __restrict__ dout)
{
    __shared__ __align__(8) float sV2[32 * 34];   // [kk][pos interleaved pairs], padded
    __shared__ float sB[32 * 128];                // [kk][d]
    int tid = threadIdx.x, tx = tid & 31, ty = tid >> 5;
    int p0 = blockIdx.x * 32, d0 = blockIdx.y * 128;

    unsigned long long acc[2][4];
    #pragma unroll
    for (int ip = 0; ip < 2; ip++)
        #pragma unroll
        for (int m = 0; m < 4; m++) acc[ip][m] = 0ull;

    for (int a0 = 0; a0 < A_DIM; a0 += 32) {
        #pragma unroll
        for (int i = tid; i < 1024; i += 256) {
            int kk = i & 31, pos = i >> 5;
            float v = g_vw[(p0 + pos) * A_DIM + a0 + kk];
            int pp = pos >> 1, c = pos & 1;
            sV2[kk * 34 + pp * 2 + c] = v;
        }
        #pragma unroll
        for (int i = tid; i < 4096; i += 256) {
            int dd = i & 127, kk = i >> 7;
            sB[kk * 128 + dd] = g_WoutT[(a0 + kk) * D_DIM + d0 + dd];
        }
        __syncthreads();
        #pragma unroll
        for (int kk = 0; kk < 32; kk++) {
            unsigned long long a0u =
                *reinterpret_cast<const unsigned long long*>(&sV2[kk * 34 + 4 * ty]);
            unsigned long long a1u =
                *reinterpret_cast<const unsigned long long*>(&sV2[kk * 34 + 4 * ty + 2]);
            #pragma unroll
            for (int m = 0; m < 4; m++) {
                float b = sB[kk * 128 + tx + 32 * m];
                unsigned long long bb = pack2(b, b);
                fma2(acc[0][m], a0u, bb);
                fma2(acc[1][m], a1u, bb);
            }
        }
        __syncthreads();
    }

    float bo[4];
    #pragma unroll
    for (int m = 0; m < 4; m++) bo[m] = b_out[d0 + tx + 32 * m];
    #pragma unroll
    for (int ip = 0; ip < 2; ip++) {
        int plo = p0 + 4 * ty + 2 * ip, phi = plo + 1;
        float hlo = g_hasenc[plo], hhi = g_hasenc[phi];
        #pragma unroll
        for (int m = 0; m < 4; m++) {
            float lo, hi; unpack2(acc[ip][m], lo, hi);
            int d = d0 + tx + 32 * m;
            dout[plo * D_DIM + d] = (lo + bo[m]) * hlo;
            dout[phi * D_DIM + d] = (hi + bo[m]) * hhi;
        }
    }
}

// ---------------------------------------------------------------------------
extern "C" void kernel_launch(void* const* d_in, const int* in_sizes, int n_in,
                              void* d_out, int out_size)
{
    const float* s2    = (const float*)d_in[0];
    const float* s1    = (const float*)d_in[1];
    const float* Win   = (const float*)d_in[2];
    const float* b_in  = (const float*)d_in[3];
    const float* Wk    = (const float*)d_in[4];
    const float* bk    = (const float*)d_in[5];
    const float* Wv    = (const float*)d_in[6];
    const float* bv    = (const float*)d_in[7];
    const float* Wout  = (const float*)d_in[8];
    const float* bout  = (const float*)d_in[9];
    const float* query = (const float*)d_in[10];
    const int*   s2m   = (const int*)d_in[11];
    const int*   s1m   = (const int*)d_in[12];
    float* out = (float*)d_out;

    int write_mask = (out_size >= OUT_MAIN + BN_POS) ? 1 : 0;

    k_u    <<<1, 256>>>(Wk, bk, Wv, bv, b_in, query);
    k_wq   <<<24, 256>>>(Win, b_in);
    k_wvin <<<dim3(4, 12), 256>>>(Wv, Win);
    k_woutT<<<192, 256>>>(Wout);
    k_main <<<1024, 256>>>(s2, s1, s2m, s1m, out, write_mask);
    k_out  <<<dim3(256, 6), 256>>>(bout, out);
}

// round 3
// speedup vs baseline: 1.4483x; 1.4483x over previous
#include <cuda_runtime.h>

// ---------------------------------------------------------------------------
// ChnAttn restructured:
//   logits[p,n,h] = t[p,n,:]·wq[:,h] + cq[h]        (wq = W_in^T W_k^T q*s)
//   attn = masked softmax over n                    (k_attn)
//   tmix[p,h,:]   = sum_n attn[p,h,n] * t[p,n,:]    (k_p2, per k-tile)
//   vw[p,a]       = W_vin[a,:]·tmix[p,h(a),:] + b_vin[a]   (k_p2 GEMM)
//   out[p,:]      = (W_out vw[p] + b_out) * has_encoder[p] (k_out)
// V-path MACs: 1.6G (vs 7.9G naive) -- attention applied BEFORE proj.
// ---------------------------------------------------------------------------

#define BN_POS   8192
#define D_DIM    768
#define A_DIM    256
#define NHEAD    8
#define SCALE    0.17677669529663687f   // 1/sqrt(32)
#define OUT_MAIN (8192*768)

// ---- device globals -------------------------------------------------------
__device__ float g_u[A_DIM * NHEAD];       // W_k^T q_s  [j][h]
__device__ float g_cqa[NHEAD];
__device__ float g_cq[NHEAD];
__device__ float g_wq[D_DIM * NHEAD];      // [d][h]
__device__ float g_WvinT[D_DIM * A_DIM];   // W_vin transposed: [k][a]
__device__ float g_bvin[A_DIM];
__device__ float g_WoutT[A_DIM * D_DIM];   // [a][d]
__device__ float g_attn[BN_POS * 40];      // [pos][h*5+n]
__device__ float g_vw[BN_POS * A_DIM];
__device__ float g_hasenc[BN_POS];

// ---- packed f32x2 helpers (used by k_out) ---------------------------------
__device__ __forceinline__ unsigned long long pack2(float lo, float hi) {
    unsigned long long r;
    asm("mov.b64 %0, {%1, %2};" : "=l"(r) : "f"(lo), "f"(hi));
    return r;
}
__device__ __forceinline__ void unpack2(unsigned long long v, float &lo, float &hi) {
    asm("mov.b64 {%0, %1}, %2;" : "=f"(lo), "=f"(hi) : "l"(v));
}
__device__ __forceinline__ void fma2(unsigned long long &d,
                                     unsigned long long a, unsigned long long b) {
    asm("fma.rn.f32x2 %0, %1, %2, %0;" : "+l"(d) : "l"(a), "l"(b));
}

// ---------------------------------------------------------------------------
// K_u: u[j][h] = sum_{i in head h} q[i]*s * W_k[i][j];  cq partial; b_vin
// ---------------------------------------------------------------------------
__global__ void k_u(const float* __restrict__ Wk, const float* __restrict__ bk,
                    const float* __restrict__ Wv, const float* __restrict__ bv,
                    const float* __restrict__ b_in, const float* __restrict__ query) {
    int j = threadIdx.x;   // 0..255
    #pragma unroll
    for (int h = 0; h < NHEAD; h++) {
        float acc = 0.f;
        #pragma unroll 8
        for (int i = 0; i < 32; i++) {
            float qs = query[h * 32 + i] * SCALE;
            acc += qs * Wk[(h * 32 + i) * A_DIM + j];
        }
        g_u[j * NHEAD + h] = acc;
    }
    if (j < NHEAD) {
        float c = 0.f;
        for (int i = 0; i < 32; i++)
            c += query[j * 32 + i] * SCALE * bk[j * 32 + i];
        g_cqa[j] = c;
    }
    float acc = 0.f;
    for (int c = 0; c < A_DIM; c++) acc += Wv[j * A_DIM + c] * b_in[c];
    g_bvin[j] = acc + bv[j];
}

// ---------------------------------------------------------------------------
// K_wq: wq[d][h] = sum_j W_in[j][d] * u[j][h];  block0 also finalizes cq
// ---------------------------------------------------------------------------
__global__ void k_wq(const float* __restrict__ Win, const float* __restrict__ b_in) {
    int d = blockIdx.x * 32 + (threadIdx.x >> 3);
    int h = threadIdx.x & 7;
    float acc = 0.f;
    #pragma unroll 8
    for (int j = 0; j < A_DIM; j++)
        acc += Win[j * D_DIM + d] * g_u[j * NHEAD + h];
    g_wq[d * NHEAD + h] = acc;
    if (blockIdx.x == 0 && threadIdx.x < NHEAD) {
        float c = g_cqa[threadIdx.x];
        for (int j = 0; j < A_DIM; j++)
            c += b_in[j] * g_u[j * NHEAD + threadIdx.x];
        g_cq[threadIdx.x] = c;
    }
}

// ---------------------------------------------------------------------------
// K_wvinT: W_vin = W_v @ W_in, stored transposed [k=d][a].  grid (4,12).
// ---------------------------------------------------------------------------
__global__ void k_wvinT(const float* __restrict__ Wv, const float* __restrict__ Win) {
    __shared__ float sWvT[32 * 65];   // [c][a] padded
    __shared__ float sWin[32 * 64];   // [c][d]
    int tid = threadIdx.x, tx = tid & 31, ty = tid >> 5;
    int a0 = blockIdx.x * 64, d0 = blockIdx.y * 64;
    float acc0[8], acc1[8];
    #pragma unroll
    for (int j = 0; j < 8; j++) { acc0[j] = 0.f; acc1[j] = 0.f; }

    for (int c0 = 0; c0 < A_DIM; c0 += 32) {
        #pragma unroll
        for (int i = tid; i < 2048; i += 256) {
            int kk = i & 31, row = i >> 5;
            sWvT[kk * 65 + row] = Wv[(a0 + row) * A_DIM + c0 + kk];
        }
        #pragma unroll
        for (int i = tid; i < 2048; i += 256) {
            int dd = i & 63, kk = i >> 6;
            sWin[kk * 64 + dd] = Win[(c0 + kk) * D_DIM + d0 + dd];
        }
        __syncthreads();
        #pragma unroll
        for (int k = 0; k < 32; k++) {
            float av0 = sWvT[k * 65 + tx];
            float av1 = sWvT[k * 65 + tx + 32];
            #pragma unroll
            for (int j = 0; j < 8; j++) {
                float b = sWin[k * 64 + ty * 8 + j];
                acc0[j] += av0 * b;
                acc1[j] += av1 * b;
            }
        }
        __syncthreads();
    }
    #pragma unroll
    for (int j = 0; j < 8; j++) {
        int d = d0 + ty * 8 + j;
        g_WvinT[d * A_DIM + a0 + tx]      = acc0[j];
        g_WvinT[d * A_DIM + a0 + tx + 32] = acc1[j];
    }
}

// ---------------------------------------------------------------------------
// K_woutT: transpose W_out (D,A) -> [a][d]
// ---------------------------------------------------------------------------
__global__ void k_woutT(const float* __restrict__ Wout) {
    int base = blockIdx.x * 1024 + threadIdx.x;
    #pragma unroll
    for (int r = 0; r < 4; r++) {
        int idx = base + r * 256;
        int d = idx >> 8, a = idx & 255;
        g_WoutT[a * D_DIM + d] = Wout[idx];
    }
}

// ---------------------------------------------------------------------------
// K_attn: logits (40960x8 over K=768) + masked softmax -> g_attn, g_hasenc.
// Block = 32 positions (160 token rows). 8 warps x 20 rows.
// ---------------------------------------------------------------------------
__global__ __launch_bounds__(256) void k_attn(
    const float* __restrict__ s2, const float* __restrict__ s1,
    const int* __restrict__ s2m, const int* __restrict__ s1m,
    float* __restrict__ dout, int write_mask)
{
    __shared__ float sWq[8][768];
    __shared__ float sL[32][5][8];
    int tid = threadIdx.x, tx = tid & 31, w = tid >> 5;
    int p0 = blockIdx.x * 32;

    #pragma unroll
    for (int r = 0; r < 24; r++) {
        int i = tid + r * 256;
        sWq[i & 7][i >> 3] = g_wq[i];
    }
    __syncthreads();

    for (int r = 0; r < 20; r++) {
        int rl = w * 20 + r;
        int pl = rl / 5, n = rl - pl * 5;
        int gp = p0 + pl;
        const float* tp = (n < 3) ? s2 + (gp * 3 + n) * D_DIM
                                  : s1 + (gp * 2 + n - 3) * D_DIM;
        float acc[8];
        #pragma unroll
        for (int h = 0; h < 8; h++) acc[h] = 0.f;
        #pragma unroll 4
        for (int j = 0; j < 24; j++) {
            int k = tx + j * 32;
            float tv = tp[k];
            #pragma unroll
            for (int h = 0; h < 8; h++) acc[h] += tv * sWq[h][k];
        }
        #pragma unroll
        for (int h = 0; h < 8; h++) {
            #pragma unroll
            for (int off = 16; off > 0; off >>= 1)
                acc[h] += __shfl_xor_sync(0xffffffffu, acc[h], off);
        }
        if (tx == 0) {
            #pragma unroll
            for (int h = 0; h < 8; h++) sL[pl][n][h] = acc[h];
        }
    }
    __syncthreads();

    // one thread per (pos, head)
    int pl = tid >> 3, h = tid & 7;
    int gp = p0 + pl;
    int m[5];
    m[0] = s2m[gp * 3 + 0];
    m[1] = s2m[gp * 3 + 1];
    m[2] = s2m[gp * 3 + 2];
    m[3] = s1m[gp * 2 + 0];
    m[4] = s1m[gp * 2 + 1];
    bool has = false;
    float cq = g_cq[h];
    float lg[5];
    #pragma unroll
    for (int n = 0; n < 5; n++) {
        float L = sL[pl][n][h] + cq;
        if (m[n] == 1) has = true; else L = -1e30f;
        lg[n] = L;
    }
    float mx = lg[0];
    #pragma unroll
    for (int n = 1; n < 5; n++) mx = fmaxf(mx, lg[n]);
    float e[5], s = 0.f;
    #pragma unroll
    for (int n = 0; n < 5; n++) { e[n] = expf(lg[n] - mx); s += e[n]; }
    float inv = 1.f / s;
    #pragma unroll
    for (int n = 0; n < 5; n++)
        g_attn[gp * 40 + h * 5 + n] = e[n] * inv;
    if (h == 0) {
        float hf = has ? 1.f : 0.f;
        g_hasenc[gp] = hf;
        if (write_mask) dout[OUT_MAIN + gp] = hf;
    }
}

// ---------------------------------------------------------------------------
// K_p2: fused tmix-build + block-diagonal V-GEMM.  Block = 32 positions.
// Per k-tile(16): build tmix[pos][h][kk] in smem, then GEMM vs W_vinT tile.
// GEMM mapping: warp w -> posg=w>>1 (8 pos), hh=w&1 (head half);
//   thread: head h_t = hh*4 + (lane>>3), cols col0..col0+3 (same head),
//   8 pos x 4 cols scalar FFMA, b via one LDS.128 (conflict-free).
// ---------------------------------------------------------------------------
__global__ __launch_bounds__(256, 2) void k_p2(
    const float* __restrict__ s2, const float* __restrict__ s1)
{
    __shared__ float sB[16 * 256];       // [kk][a]
    __shared__ float sT[32 * 8 * 18];    // [pos][h][kk], pad 18 for banks+align
    __shared__ float sAttn[32 * 40];
    __shared__ float sBv[256];

    int tid = threadIdx.x;
    int p0 = blockIdx.x * 32;

    #pragma unroll
    for (int r = 0; r < 5; r++) {
        int i = tid + r * 256;
        sAttn[i] = g_attn[p0 * 40 + i];
    }
    sBv[tid] = g_bvin[tid];

    // build-role mapping: thread -> (bpos, kk pair)
    int bpos = tid >> 3, bk2 = (tid & 7) * 2;
    const float* tptr[5];
    {
        int gp = p0 + bpos;
        tptr[0] = s2 + (gp * 3 + 0) * D_DIM;
        tptr[1] = s2 + (gp * 3 + 1) * D_DIM;
        tptr[2] = s2 + (gp * 3 + 2) * D_DIM;
        tptr[3] = s1 + (gp * 2 + 0) * D_DIM;
        tptr[4] = s1 + (gp * 2 + 1) * D_DIM;
    }

    // GEMM-role mapping
    int w = tid >> 5, l = tid & 31;
    int posg = w >> 1, hh = w & 1;
    int h_t = hh * 4 + (l >> 3);
    int col0 = h_t * 32 + (l & 7) * 4;

    float acc[8][4];
    #pragma unroll
    for (int r = 0; r < 8; r++)
        #pragma unroll
        for (int c = 0; c < 4; c++) acc[r][c] = 0.f;

    __syncthreads();

    for (int k0 = 0; k0 < D_DIM; k0 += 16) {
        // W_vinT tile
        #pragma unroll
        for (int r = 0; r < 16; r++) {
            int i = tid + r * 256;
            sB[i] = g_WvinT[k0 * 256 + i];
        }
        // tmix build: 2 kk per thread, all 8 heads
        float2 tv[5];
        #pragma unroll
        for (int n = 0; n < 5; n++)
            tv[n] = *reinterpret_cast<const float2*>(tptr[n] + k0 + bk2);
        float th[8][2];
        #pragma unroll
        for (int h = 0; h < 8; h++) { th[h][0] = 0.f; th[h][1] = 0.f; }
        #pragma unroll
        for (int n = 0; n < 5; n++) {
            #pragma unroll
            for (int h = 0; h < 8; h++) {
                float a = sAttn[bpos * 40 + h * 5 + n];
                th[h][0] += a * tv[n].x;
                th[h][1] += a * tv[n].y;
            }
        }
        #pragma unroll
        for (int h = 0; h < 8; h++)
            *reinterpret_cast<float2*>(&sT[(bpos * 8 + h) * 18 + bk2]) =
                make_float2(th[h][0], th[h][1]);
        __syncthreads();

        // GEMM: 16 kk x (8 pos x 4 cols)
        #pragma unroll
        for (int kk = 0; kk < 16; kk++) {
            float4 b4 = *reinterpret_cast<const float4*>(&sB[kk * 256 + col0]);
            #pragma unroll
            for (int r = 0; r < 8; r++) {
                float a = sT[((posg * 8 + r) * 8 + h_t) * 18 + kk];
                acc[r][0] += a * b4.x;
                acc[r][1] += a * b4.y;
                acc[r][2] += a * b4.z;
                acc[r][3] += a * b4.w;
            }
        }
        __syncthreads();
    }

    #pragma unroll
    for (int r = 0; r < 8; r++) {
        int gp = p0 + posg * 8 + r;
        #pragma unroll
        for (int c = 0; c < 4; c++)
            g_vw[gp * A_DIM + col0 + c] = acc[r][c] + sBv[col0 + c];
    }
}

// ---------------------------------------------------------------------------
// K_out: out = vw (8192x256) @ W_out^T (256x768) + b_out, masked. (unchanged)
// ---------------------------------------------------------------------------
__global__ __launch_bounds__(256, 4) void k_out(const float* __restrict__ b_out,
                                                float* __restrict__ dout)
{
    __shared__ __align__(8) float sV2[32 * 34];
    __shared__ float sB[32 * 128];
    int tid = threadIdx.x, tx = tid & 31, ty = tid >> 5;
    int p0 = blockIdx.x * 32, d0 = blockIdx.y * 128;

    unsigned long long acc[2][4];
    #pragma unroll
    for (int ip = 0; ip < 2; ip++)
        #pragma unroll
        for (int m = 0; m < 4; m++) acc[ip][m] = 0ull;

    for (int a0 = 0; a0 < A_DIM; a0 += 32) {
        #pragma unroll
        for (int i = tid; i < 1024; i += 256) {
            int kk = i & 31, pos = i >> 5;
            float v = g_vw[(p0 + pos) * A_DIM + a0 + kk];
            int pp = pos >> 1, c = pos & 1;
            sV2[kk * 34 + pp * 2 + c] = v;
        }
        #pragma unroll
        for (int i = tid; i < 4096; i += 256) {
            int dd = i & 127, kk = i >> 7;
            sB[kk * 128 + dd] = g_WoutT[(a0 + kk) * D_DIM + d0 + dd];
        }
        __syncthreads();
        #pragma unroll
        for (int kk = 0; kk < 32; kk++) {
            unsigned long long a0u =
                *reinterpret_cast<const unsigned long long*>(&sV2[kk * 34 + 4 * ty]);
            unsigned long long a1u =
                *reinterpret_cast<const unsigned long long*>(&sV2[kk * 34 + 4 * ty + 2]);
            #pragma unroll
            for (int m = 0; m < 4; m++) {
                float b = sB[kk * 128 + tx + 32 * m];
                unsigned long long bb = pack2(b, b);
                fma2(acc[0][m], a0u, bb);
                fma2(acc[1][m], a1u, bb);
            }
        }
        __syncthreads();
    }

    float bo[4];
    #pragma unroll
    for (int m = 0; m < 4; m++) bo[m] = b_out[d0 + tx + 32 * m];
    #pragma unroll
    for (int ip = 0; ip < 2; ip++) {
        int plo = p0 + 4 * ty + 2 * ip, phi = plo + 1;
        float hlo = g_hasenc[plo], hhi = g_hasenc[phi];
        #pragma unroll
        for (int m = 0; m < 4; m++) {
            float lo, hi; unpack2(acc[ip][m], lo, hi);
            int d = d0 + tx + 32 * m;
            dout[plo * D_DIM + d] = (lo + bo[m]) * hlo;
            dout[phi * D_DIM + d] = (hi + bo[m]) * hhi;
        }
    }
}

// ---------------------------------------------------------------------------
extern "C" void kernel_launch(void* const* d_in, const int* in_sizes, int n_in,
                              void* d_out, int out_size)
{
    const float* s2    = (const float*)d_in[0];
    const float* s1    = (const float*)d_in[1];
    const float* Win   = (const float*)d_in[2];
    const float* b_in  = (const float*)d_in[3];
    const float* Wk    = (const float*)d_in[4];
    const float* bk    = (const float*)d_in[5];
    const float* Wv    = (const float*)d_in[6];
    const float* bv    = (const float*)d_in[7];
    const float* Wout  = (const float*)d_in[8];
    const float* bout  = (const float*)d_in[9];
    const float* query = (const float*)d_in[10];
    const int*   s2m   = (const int*)d_in[11];
    const int*   s1m   = (const int*)d_in[12];
    float* out = (float*)d_out;

    int write_mask = (out_size >= OUT_MAIN + BN_POS) ? 1 : 0;

    k_u    <<<1, 256>>>(Wk, bk, Wv, bv, b_in, query);
    k_wq   <<<24, 256>>>(Win, b_in);
    k_wvinT<<<dim3(4, 12), 256>>>(Wv, Win);
    k_woutT<<<192, 256>>>(Wout);
    k_attn <<<256, 256>>>(s2, s1, s2m, s1m, out, write_mask);
    k_p2   <<<256, 256>>>(s2, s1);
    k_out  <<<dim3(256, 6), 256>>>(bout, out);
}

// round 4
// speedup vs baseline: 1.5262x; 1.0538x over previous
#include <cuda_runtime.h>

// ---------------------------------------------------------------------------
// ChnAttn restructured (R4):
//   pre:  g_u = W_k^T q*s ; wq = W_in^T g_u ; cq ; W_vinT = (W_v W_in)^T ;
//         b_vin ; W_outT (tiled transpose)
//   k_fused (per 32 positions):
//     pass1: logits[p,n,h] = t·wq + cq ; masked softmax -> sAttnT (smem)
//     pass2: per k-tile(8): tmix[p,h,kk] = sum_n attn*t  (dup (t,t) u64)
//            vw[p,a] = sum_k tmix[p,h(a),k] * W_vinT[k,a]   via fma.f32x2
//   k_out: out = vw @ W_outT + b_out, masked by has_encoder  (fma.f32x2)
// ---------------------------------------------------------------------------

#define BN_POS   8192
#define D_DIM    768
#define A_DIM    256
#define NHEAD    8
#define SCALE    0.17677669529663687f   // 1/sqrt(32)
#define OUT_MAIN (8192*768)

typedef unsigned long long u64;

// ---- device globals -------------------------------------------------------
__device__ float g_u[A_DIM * NHEAD];       // [j][h]
__device__ float g_cqa[NHEAD];
__device__ float g_cq[NHEAD];
__device__ float g_wq[D_DIM * NHEAD];      // [d][h]  (wq^T per-d rows)
__device__ float g_WvinT[D_DIM * A_DIM];   // [k][a]
__device__ float g_bvin[A_DIM];
__device__ float g_WoutT[A_DIM * D_DIM];   // [a][d]
__device__ float g_vw[BN_POS * A_DIM];
__device__ float g_hasenc[BN_POS];

// ---- packed f32x2 helpers -------------------------------------------------
__device__ __forceinline__ u64 pack2(float lo, float hi) {
    u64 r;
    asm("mov.b64 %0, {%1, %2};" : "=l"(r) : "f"(lo), "f"(hi));
    return r;
}
__device__ __forceinline__ void unpack2(u64 v, float &lo, float &hi) {
    asm("mov.b64 {%0, %1}, %2;" : "=f"(lo), "=f"(hi) : "l"(v));
}
__device__ __forceinline__ void fma2(u64 &d, u64 a, u64 b) {
    asm("fma.rn.f32x2 %0, %1, %2, %0;" : "+l"(d) : "l"(a), "l"(b));
}

// ---------------------------------------------------------------------------
// K_pre1: grid 17.  blocks 0-7: g_u ; 8-15: g_bvin ; 16: g_cqa
// ---------------------------------------------------------------------------
__global__ void k_pre1(const float* __restrict__ Wk, const float* __restrict__ bk,
                       const float* __restrict__ Wv, const float* __restrict__ bv,
                       const float* __restrict__ b_in, const float* __restrict__ query) {
    int b = blockIdx.x, tid = threadIdx.x;
    if (b < 8) {
        int j = b * 32 + (tid >> 3), h = tid & 7;
        float acc = 0.f;
        #pragma unroll 8
        for (int i = 0; i < 32; i++)
            acc += query[h * 32 + i] * SCALE * Wk[(h * 32 + i) * A_DIM + j];
        g_u[j * NHEAD + h] = acc;
    } else if (b < 16) {
        __shared__ float s[32][8];
        int a = (b - 8) * 32 + (tid >> 3), part = tid & 7;
        float acc = 0.f;
        #pragma unroll 8
        for (int c = part * 32; c < part * 32 + 32; c++)
            acc += Wv[a * A_DIM + c] * b_in[c];
        s[tid >> 3][part] = acc;
        __syncthreads();
        if (tid < 32) {
            int aa = (b - 8) * 32 + tid;
            float t = bv[aa];
            #pragma unroll
            for (int p = 0; p < 8; p++) t += s[tid][p];
            g_bvin[aa] = t;
        }
    } else {
        if (tid < NHEAD) {
            float c = 0.f;
            for (int i = 0; i < 32; i++)
                c += query[tid * 32 + i] * SCALE * bk[tid * 32 + i];
            g_cqa[tid] = c;
        }
    }
}

// ---------------------------------------------------------------------------
// K_wq: grid 3 x 256.  wq[d][h] = sum_j Win[j][d] * g_u[j][h]  (coalesced d)
// ---------------------------------------------------------------------------
__global__ void k_wq(const float* __restrict__ Win, const float* __restrict__ b_in) {
    __shared__ float su[2048];
    int tid = threadIdx.x;
    #pragma unroll
    for (int r = 0; r < 8; r++) su[tid + r * 256] = g_u[tid + r * 256];
    __syncthreads();
    int d = blockIdx.x * 256 + tid;
    float acc[8];
    #pragma unroll
    for (int h = 0; h < 8; h++) acc[h] = 0.f;
    #pragma unroll 4
    for (int j = 0; j < A_DIM; j++) {
        float wv = Win[j * D_DIM + d];
        float4 u0 = *reinterpret_cast<const float4*>(&su[j * 8]);
        float4 u1 = *reinterpret_cast<const float4*>(&su[j * 8 + 4]);
        acc[0] += wv * u0.x; acc[1] += wv * u0.y;
        acc[2] += wv * u0.z; acc[3] += wv * u0.w;
        acc[4] += wv * u1.x; acc[5] += wv * u1.y;
        acc[6] += wv * u1.z; acc[7] += wv * u1.w;
    }
    #pragma unroll
    for (int h = 0; h < 8; h++) g_wq[d * 8 + h] = acc[h];
    if (blockIdx.x == 0 && tid < NHEAD) {
        float c = g_cqa[tid];
        for (int j = 0; j < A_DIM; j++) c += b_in[j] * su[j * 8 + tid];
        g_cq[tid] = c;
    }
}

// ---------------------------------------------------------------------------
// K_wvinT: W_vin = W_v @ W_in, stored transposed [k=d][a].  grid (4,12).
// ---------------------------------------------------------------------------
__global__ void k_wvinT(const float* __restrict__ Wv, const float* __restrict__ Win) {
    __shared__ float sWvT[32 * 65];
    __shared__ float sWin[32 * 64];
    int tid = threadIdx.x, tx = tid & 31, ty = tid >> 5;
    int a0 = blockIdx.x * 64, d0 = blockIdx.y * 64;
    float acc0[8], acc1[8];
    #pragma unroll
    for (int j = 0; j < 8; j++) { acc0[j] = 0.f; acc1[j] = 0.f; }

    for (int c0 = 0; c0 < A_DIM; c0 += 32) {
        #pragma unroll
        for (int i = tid; i < 2048; i += 256) {
            int kk = i & 31, row = i >> 5;
            sWvT[kk * 65 + row] = Wv[(a0 + row) * A_DIM + c0 + kk];
        }
        #pragma unroll
        for (int i = tid; i < 2048; i += 256) {
            int dd = i & 63, kk = i >> 6;
            sWin[kk * 64 + dd] = Win[(c0 + kk) * D_DIM + d0 + dd];
        }
        __syncthreads();
        #pragma unroll
        for (int k = 0; k < 32; k++) {
            float av0 = sWvT[k * 65 + tx];
            float av1 = sWvT[k * 65 + tx + 32];
            #pragma unroll
            for (int j = 0; j < 8; j++) {
                float b = sWin[k * 64 + ty * 8 + j];
                acc0[j] += av0 * b;
                acc1[j] += av1 * b;
            }
        }
        __syncthreads();
    }
    #pragma unroll
    for (int j = 0; j < 8; j++) {
        int d = d0 + ty * 8 + j;
        g_WvinT[d * A_DIM + a0 + tx]      = acc0[j];
        g_WvinT[d * A_DIM + a0 + tx + 32] = acc1[j];
    }
}

// ---------------------------------------------------------------------------
// K_woutT: tiled 32x32 transpose W_out (D,A) -> [a][d]; both sides coalesced.
// grid (24, 8), 256 threads.
// ---------------------------------------------------------------------------
__global__ void k_woutT(const float* __restrict__ Wout) {
    __shared__ float s[32][33];
    int tid = threadIdx.x, c = tid & 31, r = tid >> 5;
    int d0 = blockIdx.x * 32, a0 = blockIdx.y * 32;
    #pragma unroll
    for (int p = 0; p < 4; p++)
        s[r + p * 8][c] = Wout[(d0 + r + p * 8) * A_DIM + a0 + c];
    __syncthreads();
    #pragma unroll
    for (int p = 0; p < 4; p++)
        g_WoutT[(a0 + r + p * 8) * D_DIM + d0 + c] = s[c][r + p * 8];
}

// ---------------------------------------------------------------------------
// K_fused: per-block 32 positions.
//   pass1: logits (8 warps x 20 token-rows, float4 loads) + masked softmax
//   pass2: 96 k-tiles of 8: tmix build (dup u64) + block-diag V-GEMM (fma2)
// smem_raw is reused: pass1 {sWq 24576 | sL 5120}, pass2 {sT2 18432 | sB 8192}
// ---------------------------------------------------------------------------
__global__ __launch_bounds__(256, 3) void k_fused(
    const float* __restrict__ s2, const float* __restrict__ s1,
    const int* __restrict__ s2m, const int* __restrict__ s1m,
    float* __restrict__ dout, int write_mask)
{
    __shared__ __align__(16) unsigned char smem_raw[29696];
    __shared__ float sAttnT[32 * 40];   // [pos][n*8+h]
    __shared__ float sBv[256];

    int tid = threadIdx.x, tx = tid & 31, w = tid >> 5;
    int p0 = blockIdx.x * 32;

    // ---------------- pass 1: logits ----------------
    float* sWq = reinterpret_cast<float*>(smem_raw);            // [8][768]
    float* sL  = reinterpret_cast<float*>(smem_raw + 24576);    // [32][5][8]

    #pragma unroll
    for (int r = 0; r < 24; r++) {
        int i = tid + r * 256;
        sWq[(i & 7) * 768 + (i >> 3)] = g_wq[i];
    }
    sBv[tid] = g_bvin[tid];
    __syncthreads();

    {
        int pl = w * 4, n = 0;
        for (int r = 0; r < 20; r++) {
            int gp = p0 + pl;
            const float* tp = (n < 3) ? s2 + (gp * 3 + n) * D_DIM
                                      : s1 + (gp * 2 + n - 3) * D_DIM;
            float acc[8];
            #pragma unroll
            for (int h = 0; h < 8; h++) acc[h] = 0.f;
            #pragma unroll
            for (int j = 0; j < 6; j++) {
                int k4 = tx * 4 + j * 128;
                float4 tv = *reinterpret_cast<const float4*>(tp + k4);
                #pragma unroll
                for (int h = 0; h < 8; h++) {
                    const float4 wv = *reinterpret_cast<const float4*>(&sWq[h * 768 + k4]);
                    acc[h] += tv.x * wv.x + tv.y * wv.y + tv.z * wv.z + tv.w * wv.w;
                }
            }
            #pragma unroll
            for (int h = 0; h < 8; h++) {
                #pragma unroll
                for (int off = 16; off > 0; off >>= 1)
                    acc[h] += __shfl_xor_sync(0xffffffffu, acc[h], off);
            }
            if (tx == 0) {
                #pragma unroll
                for (int h = 0; h < 8; h++) sL[(pl * 5 + n) * 8 + h] = acc[h];
            }
            if (++n == 5) { n = 0; pl++; }
        }
    }
    __syncthreads();

    // ---------------- softmax: one thread per (pos, head) ----------------
    {
        int pl = tid >> 3, h = tid & 7;
        int gp = p0 + pl;
        int m[5];
        m[0] = s2m[gp * 3 + 0];
        m[1] = s2m[gp * 3 + 1];
        m[2] = s2m[gp * 3 + 2];
        m[3] = s1m[gp * 2 + 0];
        m[4] = s1m[gp * 2 + 1];
        bool has = false;
        float cq = g_cq[h];
        float lg[5];
        #pragma unroll
        for (int n = 0; n < 5; n++) {
            float L = sL[(pl * 5 + n) * 8 + h] + cq;
            if (m[n] == 1) has = true; else L = -1e30f;
            lg[n] = L;
        }
        float mx = lg[0];
        #pragma unroll
        for (int n = 1; n < 5; n++) mx = fmaxf(mx, lg[n]);
        float e[5], s = 0.f;
        #pragma unroll
        for (int n = 0; n < 5; n++) { e[n] = expf(lg[n] - mx); s += e[n]; }
        float inv = 1.f / s;
        #pragma unroll
        for (int n = 0; n < 5; n++)
            sAttnT[pl * 40 + n * 8 + h] = e[n] * inv;
        if (h == 0) {
            float hf = has ? 1.f : 0.f;
            g_hasenc[gp] = hf;
            if (write_mask) dout[OUT_MAIN + gp] = hf;
        }
    }
    __syncthreads();   // sL reads done; smem_raw may be reused

    // ---------------- pass 2: tmix build + V-GEMM ----------------
    u64*   sT2 = reinterpret_cast<u64*>(smem_raw);              // [32*8][9] u64
    float* sB  = reinterpret_cast<float*>(smem_raw + 18432);    // [8][256]

    // build roles
    int bpos = tid >> 3, bkk = tid & 7;
    const float* tptr[5];
    {
        int gp = p0 + bpos;
        tptr[0] = s2 + (gp * 3 + 0) * D_DIM;
        tptr[1] = s2 + (gp * 3 + 1) * D_DIM;
        tptr[2] = s2 + (gp * 3 + 2) * D_DIM;
        tptr[3] = s1 + (gp * 2 + 0) * D_DIM;
        tptr[4] = s1 + (gp * 2 + 1) * D_DIM;
    }
    // GEMM roles
    int l = tid & 31;
    int posg = w >> 1, hh = w & 1;
    int h_t = hh * 4 + (l >> 3);
    int col0 = h_t * 32 + (l & 7) * 4;

    u64 acc[8][2];
    #pragma unroll
    for (int r = 0; r < 8; r++) { acc[r][0] = 0ull; acc[r][1] = 0ull; }

    for (int k0 = 0; k0 < D_DIM; k0 += 8) {
        // W_vinT tile: 8 kk x 256 a
        #pragma unroll
        for (int r = 0; r < 8; r++) {
            int i = tid + r * 256;
            sB[i] = g_WvinT[k0 * 256 + i];
        }
        // tmix build: one kk per thread, all 8 heads
        float tv[5];
        #pragma unroll
        for (int n = 0; n < 5; n++) tv[n] = tptr[n][k0 + bkk];
        float th[8];
        #pragma unroll
        for (int h = 0; h < 8; h++) th[h] = 0.f;
        #pragma unroll
        for (int n = 0; n < 5; n++) {
            float4 a0v = *reinterpret_cast<const float4*>(&sAttnT[bpos * 40 + n * 8]);
            float4 a1v = *reinterpret_cast<const float4*>(&sAttnT[bpos * 40 + n * 8 + 4]);
            th[0] += a0v.x * tv[n]; th[1] += a0v.y * tv[n];
            th[2] += a0v.z * tv[n]; th[3] += a0v.w * tv[n];
            th[4] += a1v.x * tv[n]; th[5] += a1v.y * tv[n];
            th[6] += a1v.z * tv[n]; th[7] += a1v.w * tv[n];
        }
        #pragma unroll
        for (int h = 0; h < 8; h++)
            sT2[(bpos * 8 + h) * 9 + bkk] = pack2(th[h], th[h]);
        __syncthreads();

        // GEMM: 8 kk x (8 pos x 2 col-pairs) in fma.f32x2
        #pragma unroll
        for (int kk = 0; kk < 8; kk++) {
            ulonglong2 bb = *reinterpret_cast<const ulonglong2*>(&sB[kk * 256 + col0]);
            #pragma unroll
            for (int r = 0; r < 8; r++) {
                u64 a = sT2[((posg * 8 + r) * 8 + h_t) * 9 + kk];
                fma2(acc[r][0], a, bb.x);
                fma2(acc[r][1], a, bb.y);
            }
        }
        __syncthreads();
    }

    float4 bvv;
    bvv.x = sBv[col0]; bvv.y = sBv[col0 + 1];
    bvv.z = sBv[col0 + 2]; bvv.w = sBv[col0 + 3];
    #pragma unroll
    for (int r = 0; r < 8; r++) {
        int gp = p0 + posg * 8 + r;
        float l0, h0, l1, h1;
        unpack2(acc[r][0], l0, h0);
        unpack2(acc[r][1], l1, h1);
        float4 o;
        o.x = l0 + bvv.x; o.y = h0 + bvv.y; o.z = l1 + bvv.z; o.w = h1 + bvv.w;
        *reinterpret_cast<float4*>(&g_vw[gp * A_DIM + col0]) = o;
    }
}

// ---------------------------------------------------------------------------
// K_out: out = vw (8192x256) @ W_out^T (256x768) + b_out, masked.
// b stored as duplicated (b,b) u64 pairs at fill time.
// ---------------------------------------------------------------------------
__global__ __launch_bounds__(256, 4) void k_out(const float* __restrict__ b_out,
                                                float* __restrict__ dout)
{
    __shared__ __align__(16) float sV2[32 * 34];
    __shared__ u64 sB2[32 * 128];
    int tid = threadIdx.x, tx = tid & 31, ty = tid >> 5;
    int p0 = blockIdx.x * 32, d0 = blockIdx.y * 128;

    u64 acc[2][4];
    #pragma unroll
    for (int ip = 0; ip < 2; ip++)
        #pragma unroll
        for (int m = 0; m < 4; m++) acc[ip][m] = 0ull;

    for (int a0 = 0; a0 < A_DIM; a0 += 32) {
        #pragma unroll
        for (int i = tid; i < 1024; i += 256) {
            int kk = i & 31, pos = i >> 5;
            float v = g_vw[(p0 + pos) * A_DIM + a0 + kk];
            int pp = pos >> 1, c = pos & 1;
            sV2[kk * 34 + pp * 2 + c] = v;
        }
        #pragma unroll
        for (int i = tid; i < 4096; i += 256) {
            int dd = i & 127, kk = i >> 7;
            float v = g_WoutT[(a0 + kk) * D_DIM + d0 + dd];
            sB2[kk * 128 + dd] = pack2(v, v);
        }
        __syncthreads();
        #pragma unroll
        for (int kk = 0; kk < 32; kk++) {
            u64 a0u = *reinterpret_cast<const u64*>(&sV2[kk * 34 + 4 * ty]);
            u64 a1u = *reinterpret_cast<const u64*>(&sV2[kk * 34 + 4 * ty + 2]);
            #pragma unroll
            for (int m = 0; m < 4; m++) {
                u64 bb = sB2[kk * 128 + tx + 32 * m];
                fma2(acc[0][m], a0u, bb);
                fma2(acc[1][m], a1u, bb);
            }
        }
        __syncthreads();
    }

    float bo[4];
    #pragma unroll
    for (int m = 0; m < 4; m++) bo[m] = b_out[d0 + tx + 32 * m];
    #pragma unroll
    for (int ip = 0; ip < 2; ip++) {
        int plo = p0 + 4 * ty + 2 * ip, phi = plo + 1;
        float hlo = g_hasenc[plo], hhi = g_hasenc[phi];
        #pragma unroll
        for (int m = 0; m < 4; m++) {
            float lo, hi;
            unpack2(acc[ip][m], lo, hi);
            int d = d0 + tx + 32 * m;
            dout[plo * D_DIM + d] = (lo + bo[m]) * hlo;
            dout[phi * D_DIM + d] = (hi + bo[m]) * hhi;
        }
    }
}

// ---------------------------------------------------------------------------
extern "C" void kernel_launch(void* const* d_in, const int* in_sizes, int n_in,
                              void* d_out, int out_size)
{
    const float* s2    = (const float*)d_in[0];
    const float* s1    = (const float*)d_in[1];
    const float* Win   = (const float*)d_in[2];
    const float* b_in  = (const float*)d_in[3];
    const float* Wk    = (const float*)d_in[4];
    const float* bk    = (const float*)d_in[5];
    const float* Wv    = (const float*)d_in[6];
    const float* bv    = (const float*)d_in[7];
    const float* Wout  = (const float*)d_in[8];
    const float* bout  = (const float*)d_in[9];
    const float* query = (const float*)d_in[10];
    const int*   s2m   = (const int*)d_in[11];
    const int*   s1m   = (const int*)d_in[12];
    float* out = (float*)d_out;

    int write_mask = (out_size >= OUT_MAIN + BN_POS) ? 1 : 0;

    k_pre1 <<<17, 256>>>(Wk, bk, Wv, bv, b_in, query);
    k_wq   <<<3, 256>>>(Win, b_in);
    k_wvinT<<<dim3(4, 12), 256>>>(Wv, Win);
    k_woutT<<<dim3(24, 8), 256>>>(Wout);
    k_fused<<<256, 256>>>(s2, s1, s2m, s1m, out, write_mask);
    k_out  <<<dim3(256, 6), 256>>>(bout, out);
}

// round 5
// speedup vs baseline: 1.7879x; 1.1715x over previous
#include <cuda_runtime.h>

// ---------------------------------------------------------------------------
// ChnAttn (R5): register-blocked f32x2-over-position-pairs GEMMs.
//   pre:   g_u, cq, b_vin, wq, W_vinT, W_outT
//   k_fused (64 pos/CTA): pass1 logits+softmax, pass2 tmix-build + V-GEMM
//   k_out  (64 pos x 256 d): out = vw @ W_outT + b_out, masked
// ---------------------------------------------------------------------------

#define BN_POS   8192
#define D_DIM    768
#define A_DIM    256
#define NHEAD    8
#define SCALE    0.17677669529663687f   // 1/sqrt(32)
#define OUT_MAIN (8192*768)
#define PBLK     64

typedef unsigned long long u64;

// ---- device globals -------------------------------------------------------
__device__ float g_u[A_DIM * NHEAD];
__device__ float g_cqa[NHEAD];
__device__ float g_cq[NHEAD];
__device__ float g_wq[D_DIM * NHEAD];      // [d][h], h contiguous
__device__ float g_WvinT[D_DIM * A_DIM];   // [k][a]
__device__ float g_bvin[A_DIM];
__device__ float g_WoutT[A_DIM * D_DIM];   // [a][d]
__device__ float g_vw[BN_POS * A_DIM];
__device__ float g_hasenc[BN_POS];

// ---- packed f32x2 helpers -------------------------------------------------
__device__ __forceinline__ u64 pack2(float lo, float hi) {
    u64 r;
    asm("mov.b64 %0, {%1, %2};" : "=l"(r) : "f"(lo), "f"(hi));
    return r;
}
__device__ __forceinline__ void unpack2(u64 v, float &lo, float &hi) {
    asm("mov.b64 {%0, %1}, %2;" : "=f"(lo), "=f"(hi) : "l"(v));
}
__device__ __forceinline__ void fma2(u64 &d, u64 a, u64 b) {
    asm("fma.rn.f32x2 %0, %1, %2, %0;" : "+l"(d) : "l"(a), "l"(b));
}
__device__ __forceinline__ u64 add2(u64 a, u64 b) {
    u64 r;
    asm("add.rn.f32x2 %0, %1, %2;" : "=l"(r) : "l"(a), "l"(b));
    return r;
}

// ---------------------------------------------------------------------------
// K_pre1: grid 209.
//   blocks 0-7: g_u ; 8-15: g_bvin ; 16: g_cqa ; 17-208: W_out transpose
// ---------------------------------------------------------------------------
__global__ void k_pre1(const float* __restrict__ Wk, const float* __restrict__ bk,
                       const float* __restrict__ Wv, const float* __restrict__ bv,
                       const float* __restrict__ b_in, const float* __restrict__ query,
                       const float* __restrict__ Wout) {
    __shared__ float s[32][33];
    int b = blockIdx.x, tid = threadIdx.x;
    if (b < 8) {
        int j = b * 32 + (tid >> 3), h = tid & 7;
        float acc = 0.f;
        #pragma unroll 8
        for (int i = 0; i < 32; i++)
            acc += query[h * 32 + i] * SCALE * Wk[(h * 32 + i) * A_DIM + j];
        g_u[j * NHEAD + h] = acc;
    } else if (b < 16) {
        int a = (b - 8) * 32 + (tid >> 3), part = tid & 7;
        float acc = 0.f;
        #pragma unroll 8
        for (int c = part * 32; c < part * 32 + 32; c++)
            acc += Wv[a * A_DIM + c] * b_in[c];
        s[tid >> 3][part] = acc;
        __syncthreads();
        if (tid < 32) {
            int aa = (b - 8) * 32 + tid;
            float t = bv[aa];
            #pragma unroll
            for (int p = 0; p < 8; p++) t += s[tid][p];
            g_bvin[aa] = t;
        }
    } else if (b == 16) {
        if (tid < NHEAD) {
            float c = 0.f;
            for (int i = 0; i < 32; i++)
                c += query[tid * 32 + i] * SCALE * bk[tid * 32 + i];
            g_cqa[tid] = c;
        }
    } else {
        int t = b - 17;                     // 0..191 = 24 x 8 tiles
        int bx = t % 24, by = t / 24;
        int c = tid & 31, r = tid >> 5;
        int d0 = bx * 32, a0 = by * 32;
        #pragma unroll
        for (int p = 0; p < 4; p++)
            s[r + p * 8][c] = Wout[(d0 + r + p * 8) * A_DIM + a0 + c];
        __syncthreads();
        #pragma unroll
        for (int p = 0; p < 4; p++)
            g_WoutT[(a0 + r + p * 8) * D_DIM + d0 + c] = s[c][r + p * 8];
    }
}

// ---------------------------------------------------------------------------
// K_wq: grid 3 x 256.  wq[d][h] = sum_j Win[j][d] * g_u[j][h]
// ---------------------------------------------------------------------------
__global__ void k_wq(const float* __restrict__ Win, const float* __restrict__ b_in) {
    __shared__ float su[2048];
    int tid = threadIdx.x;
    #pragma unroll
    for (int r = 0; r < 8; r++) su[tid + r * 256] = g_u[tid + r * 256];
    __syncthreads();
    int d = blockIdx.x * 256 + tid;
    float acc[8];
    #pragma unroll
    for (int h = 0; h < 8; h++) acc[h] = 0.f;
    #pragma unroll 4
    for (int j = 0; j < A_DIM; j++) {
        float wv = Win[j * D_DIM + d];
        float4 u0 = *reinterpret_cast<const float4*>(&su[j * 8]);
        float4 u1 = *reinterpret_cast<const float4*>(&su[j * 8 + 4]);
        acc[0] += wv * u0.x; acc[1] += wv * u0.y;
        acc[2] += wv * u0.z; acc[3] += wv * u0.w;
        acc[4] += wv * u1.x; acc[5] += wv * u1.y;
        acc[6] += wv * u1.z; acc[7] += wv * u1.w;
    }
    #pragma unroll
    for (int h = 0; h < 8; h++) g_wq[d * 8 + h] = acc[h];
    if (blockIdx.x == 0 && tid < NHEAD) {
        float c = g_cqa[tid];
        for (int j = 0; j < A_DIM; j++) c += b_in[j] * su[j * 8 + tid];
        g_cq[tid] = c;
    }
}

// ---------------------------------------------------------------------------
// K_wvinT: W_vin = W_v @ W_in, stored [k=d][a].  grid (4,12).
// ---------------------------------------------------------------------------
__global__ void k_wvinT(const float* __restrict__ Wv, const float* __restrict__ Win) {
    __shared__ float sWvT[32 * 65];
    __shared__ float sWin[32 * 64];
    int tid = threadIdx.x, tx = tid & 31, ty = tid >> 5;
    int a0 = blockIdx.x * 64, d0 = blockIdx.y * 64;
    float acc0[8], acc1[8];
    #pragma unroll
    for (int j = 0; j < 8; j++) { acc0[j] = 0.f; acc1[j] = 0.f; }

    for (int c0 = 0; c0 < A_DIM; c0 += 32) {
        #pragma unroll
        for (int i = tid; i < 2048; i += 256) {
            int kk = i & 31, row = i >> 5;
            sWvT[kk * 65 + row] = Wv[(a0 + row) * A_DIM + c0 + kk];
        }
        #pragma unroll
        for (int i = tid; i < 2048; i += 256) {
            int dd = i & 63, kk = i >> 6;
            sWin[kk * 64 + dd] = Win[(c0 + kk) * D_DIM + d0 + dd];
        }
        __syncthreads();
        #pragma unroll
        for (int k = 0; k < 32; k++) {
            float av0 = sWvT[k * 65 + tx];
            float av1 = sWvT[k * 65 + tx + 32];
            #pragma unroll
            for (int j = 0; j < 8; j++) {
                float b = sWin[k * 64 + ty * 8 + j];
                acc0[j] += av0 * b;
                acc1[j] += av1 * b;
            }
        }
        __syncthreads();
    }
    #pragma unroll
    for (int j = 0; j < 8; j++) {
        int d = d0 + ty * 8 + j;
        g_WvinT[d * A_DIM + a0 + tx]      = acc0[j];
        g_WvinT[d * A_DIM + a0 + tx + 32] = acc1[j];
    }
}

// ---------------------------------------------------------------------------
// K_fused: 64 positions per CTA, 256 threads, grid 128.
// sT layout: [kk][h][pos] floats, strides 548 / 68 (bank-engineered).
// sAttnT:    [pos][n*8+h] floats, stride 44.
// ---------------------------------------------------------------------------
#define T_KS 548
#define T_HS 68
#define AT_S 44

__global__ __launch_bounds__(256) void k_fused(
    const float* __restrict__ s2, const float* __restrict__ s1,
    const int* __restrict__ s2m, const int* __restrict__ s1m,
    float* __restrict__ dout, int write_mask)
{
    __shared__ __align__(16) unsigned char sm_raw[34816];
    __shared__ float sAttnT[PBLK * AT_S];   // 11264 B
    __shared__ float sBv[256];

    int tid = threadIdx.x, tx = tid & 31, w = tid >> 5;
    int p0 = blockIdx.x * PBLK;

    // ================= pass 1: logits =================
    u64*   sWq2u = reinterpret_cast<u64*>(sm_raw);            // [hp][d] 3072 u64
    float* sLf   = reinterpret_cast<float*>(sm_raw + 24576);  // [row][h] 320x8
    u64*   sLu   = reinterpret_cast<u64*>(sm_raw + 24576);

    // wq -> smem as head-pair u64, hp-major: sWq2u[hp*768 + d]
    {
        const u64* gwu = reinterpret_cast<const u64*>(g_wq);
        #pragma unroll
        for (int r = 0; r < 12; r++) {
            int i = tid + r * 256;          // i = hp*768 + d
            int hp = i / 768, d = i - hp * 768;
            sWq2u[i] = gwu[d * 4 + hp];
        }
    }
    sBv[tid] = g_bvin[tid];
    __syncthreads();

    #pragma unroll 1
    for (int step = 0; step < 10; step++) {
        const float* tp[4];
        int rows[4];
        #pragma unroll
        for (int rr = 0; rr < 4; rr++) {
            int row = step * 32 + w * 4 + rr;
            rows[rr] = row;
            int pos = row / 5, n = row - pos * 5;
            int gp = p0 + pos;
            tp[rr] = (n < 3) ? s2 + (gp * 3 + n) * D_DIM
                             : s1 + (gp * 2 + n - 3) * D_DIM;
        }
        u64 acc[4][4];
        #pragma unroll
        for (int rr = 0; rr < 4; rr++)
            #pragma unroll
            for (int hp = 0; hp < 4; hp++) acc[rr][hp] = 0ull;

        #pragma unroll 4
        for (int j = 0; j < 24; j++) {
            int k = tx + j * 32;
            #pragma unroll
            for (int rr = 0; rr < 4; rr++) {
                float tv = tp[rr][k];
                u64 td = pack2(tv, tv);
                fma2(acc[rr][0], td, sWq2u[0 * 768 + k]);
                fma2(acc[rr][1], td, sWq2u[1 * 768 + k]);
                fma2(acc[rr][2], td, sWq2u[2 * 768 + k]);
                fma2(acc[rr][3], td, sWq2u[3 * 768 + k]);
            }
        }
        // warp reduce (packed)
        #pragma unroll
        for (int off = 16; off > 0; off >>= 1) {
            #pragma unroll
            for (int rr = 0; rr < 4; rr++)
                #pragma unroll
                for (int hp = 0; hp < 4; hp++)
                    acc[rr][hp] = add2(acc[rr][hp],
                                       __shfl_xor_sync(0xffffffffu, acc[rr][hp], off));
        }
        if (tx == 0) {
            #pragma unroll
            for (int rr = 0; rr < 4; rr++)
                #pragma unroll
                for (int hp = 0; hp < 4; hp++)
                    sLu[rows[rr] * 4 + hp] = acc[rr][hp];
        }
    }
    __syncthreads();

    // ================= softmax =================
    #pragma unroll
    for (int it = 0; it < 2; it++) {
        int idx = tid + it * 256;          // 0..511
        int pl = idx >> 3, h = idx & 7;
        int gp = p0 + pl;
        int m[5];
        m[0] = s2m[gp * 3 + 0];
        m[1] = s2m[gp * 3 + 1];
        m[2] = s2m[gp * 3 + 2];
        m[3] = s1m[gp * 2 + 0];
        m[4] = s1m[gp * 2 + 1];
        bool has = false;
        float cq = g_cq[h];
        float lg[5];
        #pragma unroll
        for (int n = 0; n < 5; n++) {
            float L = sLf[(pl * 5 + n) * 8 + h] + cq;
            if (m[n] == 1) has = true; else L = -1e30f;
            lg[n] = L;
        }
        float mx = lg[0];
        #pragma unroll
        for (int n = 1; n < 5; n++) mx = fmaxf(mx, lg[n]);
        float e[5], sm = 0.f;
        #pragma unroll
        for (int n = 0; n < 5; n++) { e[n] = expf(lg[n] - mx); sm += e[n]; }
        float inv = 1.f / sm;
        #pragma unroll
        for (int n = 0; n < 5; n++)
            sAttnT[pl * AT_S + n * 8 + h] = e[n] * inv;
        if (h == 0) {
            float hf = has ? 1.f : 0.f;
            g_hasenc[gp] = hf;
            if (write_mask) dout[OUT_MAIN + gp] = hf;
        }
    }
    __syncthreads();   // sLf done; sm_raw reused below

    // ================= pass 2: tmix build + V-GEMM =================
    float* sT = reinterpret_cast<float*>(sm_raw);             // [kk][h][pos]
    float* sB = reinterpret_cast<float*>(sm_raw + 17504);     // [kk][a] 8x256

    // build roles
    int bpos = tid >> 2;
    int bkk0 = (tid & 3) * 2;
    const float* tptr[5];
    {
        int gp = p0 + bpos;
        tptr[0] = s2 + (gp * 3 + 0) * D_DIM;
        tptr[1] = s2 + (gp * 3 + 1) * D_DIM;
        tptr[2] = s2 + (gp * 3 + 2) * D_DIM;
        tptr[3] = s1 + (gp * 2 + 0) * D_DIM;
        tptr[4] = s1 + (gp * 2 + 1) * D_DIM;
    }
    // GEMM roles: warp w -> pos 8w..8w+7 (4 pairs); lane: head + col-quad
    int l = tid & 31;
    int h_t = l >> 2;
    int col0 = h_t * 32 + (l & 3) * 8;

    u64 acc[4][8];
    #pragma unroll
    for (int r = 0; r < 4; r++)
        #pragma unroll
        for (int j = 0; j < 8; j++) acc[r][j] = 0ull;

    #pragma unroll 1
    for (int k0 = 0; k0 < D_DIM; k0 += 8) {
        // sB fill
        #pragma unroll
        for (int r = 0; r < 8; r++) {
            int i = tid + r * 256;
            sB[i] = g_WvinT[k0 * 256 + i];
        }
        // tmix build: 2 kk per thread (f32x2 over kk), all 8 heads
        u64 tv2[5];
        #pragma unroll
        for (int n = 0; n < 5; n++)
            tv2[n] = *reinterpret_cast<const u64*>(tptr[n] + k0 + bkk0);
        u64 th2[8];
        #pragma unroll
        for (int h = 0; h < 8; h++) th2[h] = 0ull;
        #pragma unroll
        for (int n = 0; n < 5; n++) {
            float4 a0v = *reinterpret_cast<const float4*>(&sAttnT[bpos * AT_S + n * 8]);
            float4 a1v = *reinterpret_cast<const float4*>(&sAttnT[bpos * AT_S + n * 8 + 4]);
            fma2(th2[0], pack2(a0v.x, a0v.x), tv2[n]);
            fma2(th2[1], pack2(a0v.y, a0v.y), tv2[n]);
            fma2(th2[2], pack2(a0v.z, a0v.z), tv2[n]);
            fma2(th2[3], pack2(a0v.w, a0v.w), tv2[n]);
            fma2(th2[4], pack2(a1v.x, a1v.x), tv2[n]);
            fma2(th2[5], pack2(a1v.y, a1v.y), tv2[n]);
            fma2(th2[6], pack2(a1v.z, a1v.z), tv2[n]);
            fma2(th2[7], pack2(a1v.w, a1v.w), tv2[n]);
        }
        #pragma unroll
        for (int h = 0; h < 8; h++) {
            float x, y;
            unpack2(th2[h], x, y);
            sT[bkk0 * T_KS + h * T_HS + bpos]       = x;
            sT[(bkk0 + 1) * T_KS + h * T_HS + bpos] = y;
        }
        __syncthreads();

        // GEMM: 8 kk x (4 pairs x 8 cols)
        #pragma unroll
        for (int kk = 0; kk < 8; kk++) {
            const float* tb = &sT[kk * T_KS + h_t * T_HS + 8 * w];
            ulonglong2 A01 = *reinterpret_cast<const ulonglong2*>(tb);
            ulonglong2 A23 = *reinterpret_cast<const ulonglong2*>(tb + 4);
            float4 bf0 = *reinterpret_cast<const float4*>(&sB[kk * 256 + col0]);
            float4 bf1 = *reinterpret_cast<const float4*>(&sB[kk * 256 + col0 + 4]);
            u64 bd0 = pack2(bf0.x, bf0.x), bd1 = pack2(bf0.y, bf0.y);
            u64 bd2 = pack2(bf0.z, bf0.z), bd3 = pack2(bf0.w, bf0.w);
            u64 bd4 = pack2(bf1.x, bf1.x), bd5 = pack2(bf1.y, bf1.y);
            u64 bd6 = pack2(bf1.z, bf1.z), bd7 = pack2(bf1.w, bf1.w);
            u64 Ar[4] = {A01.x, A01.y, A23.x, A23.y};
            #pragma unroll
            for (int r = 0; r < 4; r++) {
                fma2(acc[r][0], Ar[r], bd0);
                fma2(acc[r][1], Ar[r], bd1);
                fma2(acc[r][2], Ar[r], bd2);
                fma2(acc[r][3], Ar[r], bd3);
                fma2(acc[r][4], Ar[r], bd4);
                fma2(acc[r][5], Ar[r], bd5);
                fma2(acc[r][6], Ar[r], bd6);
                fma2(acc[r][7], Ar[r], bd7);
            }
        }
        __syncthreads();
    }

    // epilogue: + b_vin, store vw (pairs -> even/odd rows)
    float4 bv0 = *reinterpret_cast<const float4*>(&sBv[col0]);
    float4 bv1 = *reinterpret_cast<const float4*>(&sBv[col0 + 4]);
    #pragma unroll
    for (int r = 0; r < 4; r++) {
        int pe = p0 + 8 * w + 2 * r, po = pe + 1;
        float e[8], o[8];
        #pragma unroll
        for (int j = 0; j < 8; j++) unpack2(acc[r][j], e[j], o[j]);
        float4 ev0 = make_float4(e[0] + bv0.x, e[1] + bv0.y, e[2] + bv0.z, e[3] + bv0.w);
        float4 ev1 = make_float4(e[4] + bv1.x, e[5] + bv1.y, e[6] + bv1.z, e[7] + bv1.w);
        float4 ov0 = make_float4(o[0] + bv0.x, o[1] + bv0.y, o[2] + bv0.z, o[3] + bv0.w);
        float4 ov1 = make_float4(o[4] + bv1.x, o[5] + bv1.y, o[6] + bv1.z, o[7] + bv1.w);
        *reinterpret_cast<float4*>(&g_vw[pe * A_DIM + col0])     = ev0;
        *reinterpret_cast<float4*>(&g_vw[pe * A_DIM + col0 + 4]) = ev1;
        *reinterpret_cast<float4*>(&g_vw[po * A_DIM + col0])     = ov0;
        *reinterpret_cast<float4*>(&g_vw[po * A_DIM + col0 + 4]) = ov1;
    }
}

// ---------------------------------------------------------------------------
// K_out: tile 64 pos x 256 d, grid (128, 3), 256 threads.
// sVp: [kk][pos] pad 68; pairs contiguous.  FMA-bound pair scheme.
// ---------------------------------------------------------------------------
__global__ __launch_bounds__(256, 2) void k_out(const float* __restrict__ b_out,
                                                float* __restrict__ dout)
{
    __shared__ __align__(16) float sVp[32 * 68];   // 8704 B
    __shared__ float sB[32 * 256];                 // 32768 B
    int tid = threadIdx.x, l = tid & 31, w = tid >> 5;
    int p0 = blockIdx.x * PBLK, d0 = blockIdx.y * 256;
    int col0 = l * 8;

    u64 acc[4][8];
    #pragma unroll
    for (int r = 0; r < 4; r++)
        #pragma unroll
        for (int j = 0; j < 8; j++) acc[r][j] = 0ull;

    #pragma unroll 1
    for (int a0 = 0; a0 < A_DIM; a0 += 32) {
        // A fill: vw -> sVp[kk][pos]
        #pragma unroll
        for (int r = 0; r < 8; r++) {
            int i = tid + r * 256;
            int kk = i & 31, pos = i >> 5;
            sVp[kk * 68 + pos] = g_vw[(p0 + pos) * A_DIM + a0 + kk];
        }
        // B fill: WoutT tile [kk][dd]
        #pragma unroll
        for (int r = 0; r < 32; r++) {
            int i = tid + r * 256;
            int kk = i >> 8, dd = i & 255;
            sB[i] = g_WoutT[(a0 + kk) * D_DIM + d0 + dd];
        }
        __syncthreads();

        #pragma unroll 8
        for (int kk = 0; kk < 32; kk++) {
            const float* tb = &sVp[kk * 68 + 8 * w];
            ulonglong2 A01 = *reinterpret_cast<const ulonglong2*>(tb);
            ulonglong2 A23 = *reinterpret_cast<const ulonglong2*>(tb + 4);
            float4 bf0 = *reinterpret_cast<const float4*>(&sB[kk * 256 + col0]);
            float4 bf1 = *reinterpret_cast<const float4*>(&sB[kk * 256 + col0 + 4]);
            u64 bd0 = pack2(bf0.x, bf0.x), bd1 = pack2(bf0.y, bf0.y);
            u64 bd2 = pack2(bf0.z, bf0.z), bd3 = pack2(bf0.w, bf0.w);
            u64 bd4 = pack2(bf1.x, bf1.x), bd5 = pack2(bf1.y, bf1.y);
            u64 bd6 = pack2(bf1.z, bf1.z), bd7 = pack2(bf1.w, bf1.w);
            u64 Ar[4] = {A01.x, A01.y, A23.x, A23.y};
            #pragma unroll
            for (int r = 0; r < 4; r++) {
                fma2(acc[r][0], Ar[r], bd0);
                fma2(acc[r][1], Ar[r], bd1);
                fma2(acc[r][2], Ar[r], bd2);
                fma2(acc[r][3], Ar[r], bd3);
                fma2(acc[r][4], Ar[r], bd4);
                fma2(acc[r][5], Ar[r], bd5);
                fma2(acc[r][6], Ar[r], bd6);
                fma2(acc[r][7], Ar[r], bd7);
            }
        }
        __syncthreads();
    }

    float4 bo0 = *reinterpret_cast<const float4*>(&b_out[d0 + col0]);
    float4 bo1 = *reinterpret_cast<const float4*>(&b_out[d0 + col0 + 4]);
    #pragma unroll
    for (int r = 0; r < 4; r++) {
        int pe = p0 + 8 * w + 2 * r, po = pe + 1;
        float he = g_hasenc[pe], ho = g_hasenc[po];
        float e[8], o[8];
        #pragma unroll
        for (int j = 0; j < 8; j++) unpack2(acc[r][j], e[j], o[j]);
        float4 ev0 = make_float4((e[0] + bo0.x) * he, (e[1] + bo0.y) * he,
                                 (e[2] + bo0.z) * he, (e[3] + bo0.w) * he);
        float4 ev1 = make_float4((e[4] + bo1.x) * he, (e[5] + bo1.y) * he,
                                 (e[6] + bo1.z) * he, (e[7] + bo1.w) * he);
        float4 ov0 = make_float4((o[0] + bo0.x) * ho, (o[1] + bo0.y) * ho,
                                 (o[2] + bo0.z) * ho, (o[3] + bo0.w) * ho);
        float4 ov1 = make_float4((o[4] + bo1.x) * ho, (o[5] + bo1.y) * ho,
                                 (o[6] + bo1.z) * ho, (o[7] + bo1.w) * ho);
        *reinterpret_cast<float4*>(&dout[pe * D_DIM + d0 + col0])     = ev0;
        *reinterpret_cast<float4*>(&dout[pe * D_DIM + d0 + col0 + 4]) = ev1;
        *reinterpret_cast<float4*>(&dout[po * D_DIM + d0 + col0])     = ov0;
        *reinterpret_cast<float4*>(&dout[po * D_DIM + d0 + col0 + 4]) = ov1;
    }
}

// ---------------------------------------------------------------------------
extern "C" void kernel_launch(void* const* d_in, const int* in_sizes, int n_in,
                              void* d_out, int out_size)
{
    const float* s2    = (const float*)d_in[0];
    const float* s1    = (const float*)d_in[1];
    const float* Win   = (const float*)d_in[2];
    const float* b_in  = (const float*)d_in[3];
    const float* Wk    = (const float*)d_in[4];
    const float* bk    = (const float*)d_in[5];
    const float* Wv    = (const float*)d_in[6];
    const float* bv    = (const float*)d_in[7];
    const float* Wout  = (const float*)d_in[8];
    const float* bout  = (const float*)d_in[9];
    const float* query = (const float*)d_in[10];
    const int*   s2m   = (const int*)d_in[11];
    const int*   s1m   = (const int*)d_in[12];
    float* out = (float*)d_out;

    int write_mask = (out_size >= OUT_MAIN + BN_POS) ? 1 : 0;

    k_pre1 <<<209, 256>>>(Wk, bk, Wv, bv, b_in, query, Wout);
    k_wq   <<<3, 256>>>(Win, b_in);
    k_wvinT<<<dim3(4, 12), 256>>>(Wv, Win);
    k_fused<<<128, 256>>>(s2, s1, s2m, s1m, out, write_mask);
    k_out  <<<dim3(128, 3), 256>>>(bout, out);
}